// round 1
// baseline (speedup 1.0000x reference)
#include <cuda_runtime.h>
#include <math.h>

#define Bb 64
#define Tt 50000
#define Cc 4
#define MS 4
#define Dd 160
#define PP 25
#define LL 2000          // T / PP
#define KE 25
#define KB 9
#define KP 9
#define TILE 1000        // multiple of PP
#define NT (Tt / TILE)   // 50
#define HSIZE (Bb * LL * Dd)   // 20,480,000 floats of h
#define KK 100           // MS*PP GEMM depth

// scratch: xs laid out as GEMM rows [b*L + l][m*25 + p]
__device__ float g_xs[(size_t)Bb * LL * KK];

__device__ __forceinline__ float gelu_exact(float v) {
    return 0.5f * v * (1.0f + erff(v * 0.70710678118654752f));
}
__device__ __forceinline__ float softplus_f(float v) {
    return fmaxf(v, 0.0f) + log1pf(expf(-fabsf(v)));
}

// ---------------------------------------------------------------------------
// Kernel A: fused front pipeline
//   x = X*M ; env = dwconv25(|x|) ; burst = dwconv9(|dx|)
//   xm = .9 env + .6 burst + .2 x ; S0 = W @ xm
//   S1 = gelu(dwconv9(S0)) ; S2 = gelu(PW @ S1) ; Sm = clip(W @ (M>0))
//   xs = S2*Sm -> g_xs rows ; m_patch -> out tail
// ---------------------------------------------------------------------------
__global__ __launch_bounds__(256) void kernelA(
    const float* __restrict__ X, const float* __restrict__ Mv,
    const float* __restrict__ w_env, const float* __restrict__ w_burst,
    const float* __restrict__ syn, const float* __restrict__ w_dw,
    const float* __restrict__ w_pw, float* __restrict__ out_mpatch)
{
    __shared__ __align__(16) float sx[Cc][TILE + 40];   // x at t0-16 .. t0+1016 (1033 used)
    __shared__ float sS0[MS][TILE + 8];                 // S0 at t0-4 .. t0+1003
    __shared__ uchar4 smask[TILE];
    __shared__ unsigned char smt[TILE];
    __shared__ float sW[MS][Cc];
    __shared__ float sWe[Cc][KE], sWb[Cc][KB], sWd[MS][KP], sPW[MS][MS];

    const int tid  = threadIdx.x;
    const int tile = blockIdx.x;
    const int b    = blockIdx.y;
    const int t0   = tile * TILE;

    // ---- small weights into smem ----
    for (int i = tid; i < Cc * KE; i += 256) sWe[i / KE][i % KE] = w_env[i];
    for (int i = tid; i < Cc * KB; i += 256) sWb[i / KB][i % KB] = w_burst[i];
    for (int i = tid; i < MS * KP; i += 256) sWd[i / KP][i % KP] = w_dw[i];
    for (int i = tid; i < MS * MS; i += 256) sPW[i / MS][i % MS] = w_pw[i];
    if (tid < MS) {
        float v0 = softplus_f(syn[tid * Cc + 0]);
        float v1 = softplus_f(syn[tid * Cc + 1]);
        float v2 = softplus_f(syn[tid * Cc + 2]);
        float v3 = softplus_f(syn[tid * Cc + 3]);
        float s  = fmaxf(v0 + v1 + v2 + v3, 1e-6f);
        float inv = 1.0f / s;
        sW[tid][0] = v0 * inv; sW[tid][1] = v1 * inv;
        sW[tid][2] = v2 * inv; sW[tid][3] = v3 * inv;
    }

    // ---- load x tile (with halo 16) as float4 over channels ----
    const float4* X4 = (const float4*)(X + (size_t)b * Tt * Cc);
    const float4* M4 = (const float4*)(Mv + (size_t)b * Tt * Cc);
    for (int i = tid; i < TILE + 33; i += 256) {
        int t = t0 - 16 + i;
        float4 xv = {0.f, 0.f, 0.f, 0.f};
        uchar4 mk = {0, 0, 0, 0};
        if (t >= 0 && t < Tt) {
            float4 a = X4[t], m = M4[t];
            xv.x = a.x * m.x; xv.y = a.y * m.y; xv.z = a.z * m.z; xv.w = a.w * m.w;
            mk.x = (m.x > 0.f); mk.y = (m.y > 0.f); mk.z = (m.z > 0.f); mk.w = (m.w > 0.f);
        }
        sx[0][i] = xv.x; sx[1][i] = xv.y; sx[2][i] = xv.z; sx[3][i] = xv.w;
        int j = i - 16;
        if (j >= 0 && j < TILE) smask[j] = mk;
    }
    __syncthreads();

    // ---- phase B: env/burst/xm -> S0 ; 4 consecutive positions per thread ----
    if (tid < 252) {
        const int j0 = tid * 4;   // S0 index base; t' = t0 - 4 + j
        float s0a[MS][4];
        #pragma unroll
        for (int m = 0; m < MS; m++)
            #pragma unroll
            for (int p = 0; p < 4; p++) s0a[m][p] = 0.f;

        #pragma unroll
        for (int c = 0; c < Cc; c++) {
            float win[28];                       // sx[c][j0 .. j0+27]
            #pragma unroll
            for (int u = 0; u < 7; u++) {
                float4 v = *(const float4*)&sx[c][j0 + 4 * u];
                win[4*u] = v.x; win[4*u+1] = v.y; win[4*u+2] = v.z; win[4*u+3] = v.w;
            }
            // |dx| for sx-index u in [8,19]; dx valid for global t in [1, T)
            float dabs[12];
            #pragma unroll
            for (int u = 8; u < 20; u++) {
                int tg = t0 - 16 + j0 + u;
                float d = win[u] - win[u - 1];
                dabs[u - 8] = (tg >= 1 && tg < Tt) ? fabsf(d) : 0.f;
            }
            float env[4] = {0.f, 0.f, 0.f, 0.f};
            float bur[4] = {0.f, 0.f, 0.f, 0.f};
            #pragma unroll
            for (int k = 0; k < KE; k++) {
                float w = sWe[c][k];
                env[0] += fabsf(win[k    ]) * w;
                env[1] += fabsf(win[k + 1]) * w;
                env[2] += fabsf(win[k + 2]) * w;
                env[3] += fabsf(win[k + 3]) * w;
            }
            #pragma unroll
            for (int k = 0; k < KB; k++) {
                float w = sWb[c][k];
                bur[0] += dabs[k    ] * w;
                bur[1] += dabs[k + 1] * w;
                bur[2] += dabs[k + 2] * w;
                bur[3] += dabs[k + 3] * w;
            }
            #pragma unroll
            for (int p = 0; p < 4; p++) {
                float xmv = 0.9f * env[p] + 0.6f * bur[p] + 0.2f * win[p + 12];
                #pragma unroll
                for (int m = 0; m < MS; m++) s0a[m][p] += sW[m][c] * xmv;
            }
        }
        #pragma unroll
        for (int p = 0; p < 4; p++) {
            int j  = j0 + p;
            int tp = t0 - 4 + j;
            bool valid = (tp >= 0 && tp < Tt);
            #pragma unroll
            for (int m = 0; m < MS; m++)
                sS0[m][j] = valid ? s0a[m][p] : 0.f;
        }
    }
    __syncthreads();

    // ---- phase C: dwconv9+gelu, pointwise+gelu, mask, write xs rows ----
    for (int i = tid; i < TILE; i += 256) {
        float S1[MS];
        #pragma unroll
        for (int m = 0; m < MS; m++) {
            float a = 0.f;
            #pragma unroll
            for (int k = 0; k < KP; k++) a += sS0[m][i + k] * sWd[m][k];
            S1[m] = gelu_exact(a);
        }
        uchar4 mk = smask[i];
        float mf0 = (float)mk.x, mf1 = (float)mk.y, mf2 = (float)mk.z, mf3 = (float)mk.w;
        int t = t0 + i;
        int l = t / PP, p = t - l * PP;
        float* dst = &g_xs[((size_t)b * LL + l) * KK + p];
        float smsum = 0.f;
        #pragma unroll
        for (int o = 0; o < MS; o++) {
            float a  = sPW[o][0]*S1[0] + sPW[o][1]*S1[1] + sPW[o][2]*S1[2] + sPW[o][3]*S1[3];
            float s2 = gelu_exact(a);
            float sm = sW[o][0]*mf0 + sW[o][1]*mf1 + sW[o][2]*mf2 + sW[o][3]*mf3;
            sm = fminf(fmaxf(sm, 0.f), 1.f);
            smsum += sm;
            dst[o * PP] = s2 * sm;
        }
        smt[i] = (smsum > 0.f) ? 1 : 0;
    }
    __syncthreads();

    // ---- phase D: m_patch (40 patches per tile) ----
    if (tid < TILE / PP) {
        int s = 0;
        #pragma unroll
        for (int p = 0; p < PP; p++) s += smt[tid * PP + p];
        // mean > 0.1  <=>  s > 2.5
        out_mpatch[(size_t)b * LL + tile * (TILE / PP) + tid] = (s >= 3) ? 1.f : 0.f;
    }
}

// ---------------------------------------------------------------------------
// Kernel B: projection GEMM [128000 x 100] @ [100 x 160] + fused LayerNorm
//   block: 64 rows x 160 outputs, 160 threads, 8x8 register tile per thread
// ---------------------------------------------------------------------------
__global__ __launch_bounds__(160) void kernelB(
    const float* __restrict__ wproj, const float* __restrict__ gamma,
    const float* __restrict__ beta, float* __restrict__ out)
{
    __shared__ __align__(16) float smem[50 * 160 + 50 * 68];   // 45,600 B
    float* sWt = smem;                 // [50][160]  (k-major, d contiguous)
    float* sIn = smem + 50 * 160;      // [50][68]   (k-major, row contiguous, padded)
    __shared__ float sMu[64], sRs[64];

    const int tid  = threadIdx.x;
    const int Row0 = blockIdx.x * 64;
    const int dg = tid % 20, rg = tid / 20;
    const int d0 = dg * 8, r0 = rg * 8;

    float acc[8][8];
    #pragma unroll
    for (int i = 0; i < 8; i++)
        #pragma unroll
        for (int j = 0; j < 8; j++) acc[i][j] = 0.f;

    for (int kc = 0; kc < 2; kc++) {
        const int kb = kc * 50;
        __syncthreads();
        // weights: wproj[d][k] -> sWt[k][d]
        for (int i = tid; i < 160 * 50; i += 160) {
            int d = i / 50, kk = i % 50;
            sWt[kk * 160 + d] = wproj[d * KK + kb + kk];
        }
        // inputs: g_xs[row][k] -> sIn[k][row]
        for (int i = tid; i < 64 * 50; i += 160) {
            int rr = i / 50, kk = i % 50;
            sIn[kk * 68 + rr] = g_xs[(size_t)(Row0 + rr) * KK + kb + kk];
        }
        __syncthreads();
        #pragma unroll 5
        for (int k = 0; k < 50; k++) {
            float4 a1 = *(const float4*)&sIn[k * 68 + r0];
            float4 a2 = *(const float4*)&sIn[k * 68 + r0 + 4];
            float4 w1 = *(const float4*)&sWt[k * 160 + d0];
            float4 w2 = *(const float4*)&sWt[k * 160 + d0 + 4];
            float av[8] = {a1.x, a1.y, a1.z, a1.w, a2.x, a2.y, a2.z, a2.w};
            float wv[8] = {w1.x, w1.y, w1.z, w1.w, w2.x, w2.y, w2.z, w2.w};
            #pragma unroll
            for (int i = 0; i < 8; i++)
                #pragma unroll
                for (int j = 0; j < 8; j++)
                    acc[i][j] += av[i] * wv[j];
        }
    }
    __syncthreads();

    // stash h tile into smem (reuse) with pad-164 rows
    float* sH = smem;   // [64][164] = 41,984 B
    #pragma unroll
    for (int i = 0; i < 8; i++)
        #pragma unroll
        for (int j = 0; j < 8; j++)
            sH[(r0 + i) * 164 + d0 + j] = acc[i][j];
    __syncthreads();

    if (tid < 64) {
        float s = 0.f, ss = 0.f;
        for (int d = 0; d < Dd; d++) {
            float v = sH[tid * 164 + d];
            s += v; ss += v * v;
        }
        float mu  = s * (1.0f / Dd);
        float var = ss * (1.0f / Dd) - mu * mu;
        sMu[tid] = mu;
        sRs[tid] = rsqrtf(var + 1e-5f);
    }
    __syncthreads();

    for (int i = tid; i < 64 * Dd; i += 160) {
        int rr = i / Dd, d = i % Dd;
        float v = (sH[rr * 164 + d] - sMu[rr]) * sRs[rr] * gamma[d] + beta[d];
        out[(size_t)(Row0 + rr) * Dd + d] = v;
    }
}

// ---------------------------------------------------------------------------
extern "C" void kernel_launch(void* const* d_in, const int* in_sizes, int n_in,
                              void* d_out, int out_size)
{
    const float* X      = (const float*)d_in[0];
    const float* M      = (const float*)d_in[1];
    const float* w_env  = (const float*)d_in[2];
    const float* w_bur  = (const float*)d_in[3];
    const float* syn    = (const float*)d_in[4];
    const float* w_dw   = (const float*)d_in[5];
    const float* w_pw   = (const float*)d_in[6];
    const float* w_proj = (const float*)d_in[7];
    const float* gamma  = (const float*)d_in[8];
    const float* beta   = (const float*)d_in[9];
    float* out = (float*)d_out;

    dim3 gA(NT, Bb);
    kernelA<<<gA, 256>>>(X, M, w_env, w_bur, syn, w_dw, w_pw, out + HSIZE);
    kernelB<<<(Bb * LL) / 64, 160>>>(w_proj, gamma, beta, out);
}

// round 2
// speedup vs baseline: 1.3552x; 1.3552x over previous
#include <cuda_runtime.h>
#include <math.h>

#define Bb 64
#define Tt 50000
#define Cc 4
#define MS 4
#define Dd 160
#define PP 25
#define LL 2000          // T / PP
#define KE 25
#define KB 9
#define KP 9
#define TILE 1000        // multiple of PP
#define NT (Tt / TILE)   // 50
#define HSIZE (Bb * LL * Dd)   // 20,480,000 floats of h
#define KK 100           // MS*PP GEMM depth

// scratch: xs laid out as GEMM rows [b*L + l][m*25 + p]
__device__ float g_xs[(size_t)Bb * LL * KK];

__device__ __forceinline__ float gelu_exact(float v) {
    return 0.5f * v * (1.0f + erff(v * 0.70710678118654752f));
}
__device__ __forceinline__ float softplus_f(float v) {
    return fmaxf(v, 0.0f) + log1pf(expf(-fabsf(v)));
}

typedef unsigned long long ull;

__device__ __forceinline__ ull ffma2(ull a, ull b, ull c) {
    ull d;
    asm("fma.rn.f32x2 %0, %1, %2, %3;" : "=l"(d) : "l"(a), "l"(b), "l"(c));
    return d;
}
__device__ __forceinline__ ull bcast2(float x) {
    ull d;
    asm("mov.b64 %0, {%1, %1};" : "=l"(d) : "f"(x));
    return d;
}
union F4U { float4 v; ull u[2]; };
union UF2 { ull u; float2 f; };

// ---------------------------------------------------------------------------
// Kernel A: fused front pipeline (unchanged from round 1)
// ---------------------------------------------------------------------------
__global__ __launch_bounds__(256) void kernelA(
    const float* __restrict__ X, const float* __restrict__ Mv,
    const float* __restrict__ w_env, const float* __restrict__ w_burst,
    const float* __restrict__ syn, const float* __restrict__ w_dw,
    const float* __restrict__ w_pw, float* __restrict__ out_mpatch)
{
    __shared__ __align__(16) float sx[Cc][TILE + 40];
    __shared__ float sS0[MS][TILE + 8];
    __shared__ uchar4 smask[TILE];
    __shared__ unsigned char smt[TILE];
    __shared__ float sW[MS][Cc];
    __shared__ float sWe[Cc][KE], sWb[Cc][KB], sWd[MS][KP], sPW[MS][MS];

    const int tid  = threadIdx.x;
    const int tile = blockIdx.x;
    const int b    = blockIdx.y;
    const int t0   = tile * TILE;

    for (int i = tid; i < Cc * KE; i += 256) sWe[i / KE][i % KE] = w_env[i];
    for (int i = tid; i < Cc * KB; i += 256) sWb[i / KB][i % KB] = w_burst[i];
    for (int i = tid; i < MS * KP; i += 256) sWd[i / KP][i % KP] = w_dw[i];
    for (int i = tid; i < MS * MS; i += 256) sPW[i / MS][i % MS] = w_pw[i];
    if (tid < MS) {
        float v0 = softplus_f(syn[tid * Cc + 0]);
        float v1 = softplus_f(syn[tid * Cc + 1]);
        float v2 = softplus_f(syn[tid * Cc + 2]);
        float v3 = softplus_f(syn[tid * Cc + 3]);
        float s  = fmaxf(v0 + v1 + v2 + v3, 1e-6f);
        float inv = 1.0f / s;
        sW[tid][0] = v0 * inv; sW[tid][1] = v1 * inv;
        sW[tid][2] = v2 * inv; sW[tid][3] = v3 * inv;
    }

    const float4* X4 = (const float4*)(X + (size_t)b * Tt * Cc);
    const float4* M4 = (const float4*)(Mv + (size_t)b * Tt * Cc);
    for (int i = tid; i < TILE + 33; i += 256) {
        int t = t0 - 16 + i;
        float4 xv = {0.f, 0.f, 0.f, 0.f};
        uchar4 mk = {0, 0, 0, 0};
        if (t >= 0 && t < Tt) {
            float4 a = X4[t], m = M4[t];
            xv.x = a.x * m.x; xv.y = a.y * m.y; xv.z = a.z * m.z; xv.w = a.w * m.w;
            mk.x = (m.x > 0.f); mk.y = (m.y > 0.f); mk.z = (m.z > 0.f); mk.w = (m.w > 0.f);
        }
        sx[0][i] = xv.x; sx[1][i] = xv.y; sx[2][i] = xv.z; sx[3][i] = xv.w;
        int j = i - 16;
        if (j >= 0 && j < TILE) smask[j] = mk;
    }
    __syncthreads();

    if (tid < 252) {
        const int j0 = tid * 4;
        float s0a[MS][4];
        #pragma unroll
        for (int m = 0; m < MS; m++)
            #pragma unroll
            for (int p = 0; p < 4; p++) s0a[m][p] = 0.f;

        #pragma unroll
        for (int c = 0; c < Cc; c++) {
            float win[28];
            #pragma unroll
            for (int u = 0; u < 7; u++) {
                float4 v = *(const float4*)&sx[c][j0 + 4 * u];
                win[4*u] = v.x; win[4*u+1] = v.y; win[4*u+2] = v.z; win[4*u+3] = v.w;
            }
            float dabs[12];
            #pragma unroll
            for (int u = 8; u < 20; u++) {
                int tg = t0 - 16 + j0 + u;
                float d = win[u] - win[u - 1];
                dabs[u - 8] = (tg >= 1 && tg < Tt) ? fabsf(d) : 0.f;
            }
            float env[4] = {0.f, 0.f, 0.f, 0.f};
            float bur[4] = {0.f, 0.f, 0.f, 0.f};
            #pragma unroll
            for (int k = 0; k < KE; k++) {
                float w = sWe[c][k];
                env[0] += fabsf(win[k    ]) * w;
                env[1] += fabsf(win[k + 1]) * w;
                env[2] += fabsf(win[k + 2]) * w;
                env[3] += fabsf(win[k + 3]) * w;
            }
            #pragma unroll
            for (int k = 0; k < KB; k++) {
                float w = sWb[c][k];
                bur[0] += dabs[k    ] * w;
                bur[1] += dabs[k + 1] * w;
                bur[2] += dabs[k + 2] * w;
                bur[3] += dabs[k + 3] * w;
            }
            #pragma unroll
            for (int p = 0; p < 4; p++) {
                float xmv = 0.9f * env[p] + 0.6f * bur[p] + 0.2f * win[p + 12];
                #pragma unroll
                for (int m = 0; m < MS; m++) s0a[m][p] += sW[m][c] * xmv;
            }
        }
        #pragma unroll
        for (int p = 0; p < 4; p++) {
            int j  = j0 + p;
            int tp = t0 - 4 + j;
            bool valid = (tp >= 0 && tp < Tt);
            #pragma unroll
            for (int m = 0; m < MS; m++)
                sS0[m][j] = valid ? s0a[m][p] : 0.f;
        }
    }
    __syncthreads();

    for (int i = tid; i < TILE; i += 256) {
        float S1[MS];
        #pragma unroll
        for (int m = 0; m < MS; m++) {
            float a = 0.f;
            #pragma unroll
            for (int k = 0; k < KP; k++) a += sS0[m][i + k] * sWd[m][k];
            S1[m] = gelu_exact(a);
        }
        uchar4 mk = smask[i];
        float mf0 = (float)mk.x, mf1 = (float)mk.y, mf2 = (float)mk.z, mf3 = (float)mk.w;
        int t = t0 + i;
        int l = t / PP, p = t - l * PP;
        float* dst = &g_xs[((size_t)b * LL + l) * KK + p];
        float smsum = 0.f;
        #pragma unroll
        for (int o = 0; o < MS; o++) {
            float a  = sPW[o][0]*S1[0] + sPW[o][1]*S1[1] + sPW[o][2]*S1[2] + sPW[o][3]*S1[3];
            float s2 = gelu_exact(a);
            float sm = sW[o][0]*mf0 + sW[o][1]*mf1 + sW[o][2]*mf2 + sW[o][3]*mf3;
            sm = fminf(fmaxf(sm, 0.f), 1.f);
            smsum += sm;
            dst[o * PP] = s2 * sm;
        }
        smt[i] = (smsum > 0.f) ? 1 : 0;
    }
    __syncthreads();

    if (tid < TILE / PP) {
        int s = 0;
        #pragma unroll
        for (int p = 0; p < PP; p++) s += smt[tid * PP + p];
        out_mpatch[(size_t)b * LL + tile * (TILE / PP) + tid] = (s >= 3) ? 1.f : 0.f;
    }
}

// ---------------------------------------------------------------------------
// Kernel B v2: [128000 x 100] @ [100 x 160] + fused LayerNorm, FFMA2 path
//   block: 128 rows x 160 cols, 320 threads (16 rg x 20 dg), 8x8 per thread
//   K chunked by 25; sIn [25][132] k-major rows, sW [25][164] k-major
// ---------------------------------------------------------------------------
#define KC 25
#define SIN_STRIDE 132
#define SW_STRIDE 164
#define SIN_SIZE (KC * SIN_STRIDE)                // 3300 floats
#define SMEMB_FLOATS (SIN_SIZE + KC * SW_STRIDE)  // 3300 + 4100 = 7400 (29.6 KB)

__global__ __launch_bounds__(320, 2) void kernelB(
    const float* __restrict__ wproj, const float* __restrict__ gamma,
    const float* __restrict__ beta, float* __restrict__ out)
{
    __shared__ __align__(16) float smem[SMEMB_FLOATS];
    __shared__ float sMu[128], sRs[128];
    float* sIn = smem;              // [KC][132]
    float* sW  = smem + SIN_SIZE;   // [KC][164]

    const int tid  = threadIdx.x;
    const int Row0 = blockIdx.x * 128;
    const int dg = tid % 20, rg = tid / 20;
    const int d0 = dg * 8, r0 = rg * 8;

    ull acc[8][4];
    #pragma unroll
    for (int i = 0; i < 8; i++)
        #pragma unroll
        for (int j = 0; j < 4; j++) acc[i][j] = 0ULL;

    for (int kc = 0; kc < KK / KC; kc++) {
        const int kb = kc * KC;
        __syncthreads();
        // inputs: g_xs[row][kb+kk] -> sIn[kk][row]
        for (int i = tid; i < 128 * KC; i += 320) {
            int rr = i / KC, kk = i - rr * KC;
            sIn[kk * SIN_STRIDE + rr] = g_xs[(size_t)(Row0 + rr) * KK + kb + kk];
        }
        // weights: wproj[d][kb+kk] -> sW[kk][d]
        for (int i = tid; i < Dd * KC; i += 320) {
            int d = i / KC, kk = i - d * KC;
            sW[kk * SW_STRIDE + d] = wproj[d * KK + kb + kk];
        }
        __syncthreads();
        #pragma unroll 5
        for (int k = 0; k < KC; k++) {
            float4 a0 = *(const float4*)&sIn[k * SIN_STRIDE + r0];
            float4 a1 = *(const float4*)&sIn[k * SIN_STRIDE + r0 + 4];
            F4U w0, w1;
            w0.v = *(const float4*)&sW[k * SW_STRIDE + d0];
            w1.v = *(const float4*)&sW[k * SW_STRIDE + d0 + 4];
            float av[8] = {a0.x, a0.y, a0.z, a0.w, a1.x, a1.y, a1.z, a1.w};
            #pragma unroll
            for (int r = 0; r < 8; r++) {
                ull ap = bcast2(av[r]);
                acc[r][0] = ffma2(ap, w0.u[0], acc[r][0]);
                acc[r][1] = ffma2(ap, w0.u[1], acc[r][1]);
                acc[r][2] = ffma2(ap, w1.u[0], acc[r][2]);
                acc[r][3] = ffma2(ap, w1.u[1], acc[r][3]);
            }
        }
    }
    __syncthreads();

    // ---- fused LayerNorm: partial row sums from registers ----
    float* sSum = smem;             // [128][20]
    float* sSq  = smem + 128 * 20;  // [128][20]
    #pragma unroll
    for (int r = 0; r < 8; r++) {
        float s = 0.f, q = 0.f;
        #pragma unroll
        for (int j = 0; j < 4; j++) {
            UF2 u; u.u = acc[r][j];
            s += u.f.x + u.f.y;
            q += u.f.x * u.f.x + u.f.y * u.f.y;
        }
        sSum[(r0 + r) * 20 + dg] = s;
        sSq [(r0 + r) * 20 + dg] = q;
    }
    __syncthreads();
    if (tid < 128) {
        float s = 0.f, q = 0.f;
        #pragma unroll
        for (int j = 0; j < 20; j++) {
            s += sSum[tid * 20 + j];
            q += sSq [tid * 20 + j];
        }
        float mu  = s * (1.0f / Dd);
        float var = q * (1.0f / Dd) - mu * mu;
        sMu[tid] = mu;
        sRs[tid] = rsqrtf(var + 1e-5f);
    }
    __syncthreads();

    float gm[8], bt[8];
    #pragma unroll
    for (int j = 0; j < 8; j++) { gm[j] = gamma[d0 + j]; bt[j] = beta[d0 + j]; }

    #pragma unroll
    for (int r = 0; r < 8; r++) {
        float mu = sMu[r0 + r], rs = sRs[r0 + r];
        float v[8];
        #pragma unroll
        for (int j = 0; j < 4; j++) {
            UF2 u; u.u = acc[r][j];
            v[2*j]   = (u.f.x - mu) * rs * gm[2*j]   + bt[2*j];
            v[2*j+1] = (u.f.y - mu) * rs * gm[2*j+1] + bt[2*j+1];
        }
        float* dst = out + (size_t)(Row0 + r0 + r) * Dd + d0;
        *(float4*)(dst)     = make_float4(v[0], v[1], v[2], v[3]);
        *(float4*)(dst + 4) = make_float4(v[4], v[5], v[6], v[7]);
    }
}

// ---------------------------------------------------------------------------
extern "C" void kernel_launch(void* const* d_in, const int* in_sizes, int n_in,
                              void* d_out, int out_size)
{
    const float* X      = (const float*)d_in[0];
    const float* M      = (const float*)d_in[1];
    const float* w_env  = (const float*)d_in[2];
    const float* w_bur  = (const float*)d_in[3];
    const float* syn    = (const float*)d_in[4];
    const float* w_dw   = (const float*)d_in[5];
    const float* w_pw   = (const float*)d_in[6];
    const float* w_proj = (const float*)d_in[7];
    const float* gamma  = (const float*)d_in[8];
    const float* beta   = (const float*)d_in[9];
    float* out = (float*)d_out;

    dim3 gA(NT, Bb);
    kernelA<<<gA, 256>>>(X, M, w_env, w_bur, syn, w_dw, w_pw, out + HSIZE);
    kernelB<<<(Bb * LL) / 128, 320>>>(w_proj, gamma, beta, out);
}